// round 13
// baseline (speedup 1.0000x reference)
#include <cuda_runtime.h>

#define NS   1024
#define NB   16
#define NQ   8192
#define NDV  64
#define G    16
#define NC   (G * G)
#define QCAP 96

// Scratch (allocation-free rule: __device__ globals).
__device__ float4 g_qbuck[NB][NC * QCAP];   // bucketed queries (qx,qy,q2,orig-bits)
__device__ int    g_qcnt[NB][NC];           // zero at load; consumed->zeroed each run

// ---------------------------------------------------------------------------
// K1: query bucketing only. Linear j = q*NB+b -> fully coalesced loads.
// ---------------------------------------------------------------------------
__global__ __launch_bounds__(256)
void k1_bucket(const float* __restrict__ query_posns)    // [NQ, NB, 2]
{
    const int j = blockIdx.x * 256 + threadIdx.x;
    const float2 p = *reinterpret_cast<const float2*>(query_posns + 2 * j);
    const int b = j & (NB - 1);
    const int q = j >> 4;
    int cx = (int)(p.x * G); cx = cx < 0 ? 0 : (cx > G - 1 ? G - 1 : cx);
    int cy = (int)(p.y * G); cy = cy < 0 ? 0 : (cy > G - 1 ? G - 1 : cy);
    const int c = cy * G + cx;
    const int slot = atomicAdd(&g_qcnt[b][c], 1);
    if (slot < QCAP) {
        const float q2 = __fadd_rn(__fmul_rn(p.x, p.x), __fmul_rn(p.y, p.y));
        g_qbuck[b][c * QCAP + slot] = make_float4(p.x, p.y, q2, __int_as_float(q));
    }
}

// ---------------------------------------------------------------------------
// K2: per-block private sample binning + warp-per-cell exact 1-NN (QPT=2).
// ---------------------------------------------------------------------------
__device__ __forceinline__ void scan_range2(const float4* __restrict__ samp,
                                            int s0, int s1,
                                            float qx0, float qy0, float q20,
                                            float qx1, float qy1, float q21,
                                            float& b0, int& i0r,
                                            float& b1, int& i1r)
{
    for (int k = s0; k < s1; k++) {
        const float4 v = samp[k];             // warp-uniform address -> LDS broadcast
        const int idx = __float_as_int(v.w);
        // EXACT reference rounding: t = fma(qy,-2sy, qx*(-2sx)); d = (q2 + t) + s2
        const float t0 = __fmaf_rn(qy0, v.y, __fmul_rn(qx0, v.x));
        const float d0 = __fadd_rn(__fadd_rn(q20, t0), v.z);
        if (d0 < b0 || (d0 == b0 && idx < i0r)) { b0 = d0; i0r = idx; }
        const float t1 = __fmaf_rn(qy1, v.y, __fmul_rn(qx1, v.x));
        const float d1 = __fadd_rn(__fadd_rn(q21, t1), v.z);
        if (d1 < b1 || (d1 == b1 && idx < i1r)) { b1 = d1; i1r = idx; }
    }
}

__global__ __launch_bounds__(256)
void nn_search(const float* __restrict__ sample_vals,    // [NS, NB, NDV]
               const float* __restrict__ sample_posns,   // [NS, NB, 2]
               float* __restrict__ out)                  // [NQ, NB, NDV]
{
    __shared__ float4 s_samp[NS];          // 16 KB, cell-sorted
    __shared__ int    s_cs[NC + 1];
    __shared__ int    s_cnt[NC];
    __shared__ int    s_cur[NC];
    __shared__ int    s_wsum[8];
    __shared__ int    s_bi[8][QCAP];
    __shared__ int    s_orig[8][QCAP];

    const int tid  = threadIdx.x;
    const int lane = tid & 31;
    const int w    = tid >> 5;
    const int b    = blockIdx.x >> 5;      // batch
    const int grp  = blockIdx.x & 31;      // cell group (8 cells, one per warp)

    // ---- private sample binning: count -> scan -> scatter (all in SMEM) ----
    s_cnt[tid] = 0;
    __syncthreads();

    float2 p[4];
    int    cell[4];
#pragma unroll
    for (int k = 0; k < 4; k++) {
        const int s = tid + k * 256;
        p[k] = *reinterpret_cast<const float2*>(sample_posns + (s * NB + b) * 2);
        int cx = (int)(p[k].x * G); cx = cx < 0 ? 0 : (cx > G - 1 ? G - 1 : cx);
        int cy = (int)(p[k].y * G); cy = cy < 0 ? 0 : (cy > G - 1 ? G - 1 : cy);
        cell[k] = cy * G + cx;
        atomicAdd(&s_cnt[cell[k]], 1);
    }
    __syncthreads();

    const int cnt = s_cnt[tid];
    int incl = cnt;
#pragma unroll
    for (int ofs = 1; ofs < 32; ofs <<= 1) {
        const int t = __shfl_up_sync(0xffffffffu, incl, ofs);
        if (lane >= ofs) incl += t;
    }
    if (lane == 31) s_wsum[w] = incl;
    __syncthreads();
    if (w == 0 && lane < 8) {
        int x = s_wsum[lane];
#pragma unroll
        for (int ofs = 1; ofs < 8; ofs <<= 1) {
            const int t = __shfl_up_sync(0xffu, x, ofs);
            if (lane >= ofs) x += t;
        }
        s_wsum[lane] = x;
    }
    __syncthreads();
    const int excl = incl - cnt + (w > 0 ? s_wsum[w - 1] : 0);
    s_cs[tid]  = excl;
    s_cur[tid] = excl;
    if (tid == 0) s_cs[NC] = NS;
    __syncthreads();

#pragma unroll
    for (int k = 0; k < 4; k++) {
        const int s   = tid + k * 256;
        const int pos = atomicAdd(&s_cur[cell[k]], 1);
        // s2 with reference rounding: mul, mul, add. -2 fold bit-exact (pow2).
        const float s2 = __fadd_rn(__fmul_rn(p[k].x, p[k].x), __fmul_rn(p[k].y, p[k].y));
        s_samp[pos] = make_float4(-2.0f * p[k].x, -2.0f * p[k].y, s2, __int_as_float(s));
    }
    __syncthreads();

    // ---- warp-per-cell exact 1-NN, QPT=2 (one pass: P(n>64) ~ 6e-9) ----
    const int cell_w = grp * 8 + w;
    const int cx     = cell_w & (G - 1);
    const int cy     = cell_w >> 4;

    int n = 0;
    if (lane == 0) n = atomicExch(&g_qcnt[b][cell_w], 0);   // consume + reset invariant
    n = __shfl_sync(0xffffffffu, n, 0);
    if (n > QCAP) n = QCAP;

    const float h = 1.0f / G;
    const float4* __restrict__ qb = &g_qbuck[b][cell_w * QCAP];

    for (int base = 0; base < n; base += 64) {
        const int  i0 = base + lane;
        const int  i1 = base + 32 + lane;
        const bool a0 = (i0 < n);
        const bool a1 = (i1 < n);
        const float4 qs0 = qb[a0 ? i0 : 0];
        const float4 qs1 = qb[a1 ? i1 : 0];
        const float qx0 = qs0.x, qy0 = qs0.y, q20 = qs0.z;
        const float qx1 = qs1.x, qy1 = qs1.y, q21 = qs1.z;

        float b0 = a0 ? __int_as_float(0x7f800000) : __int_as_float(0xff800000);
        float b1 = a1 ? __int_as_float(0x7f800000) : __int_as_float(0xff800000);
        int  bi0 = 0, bi1 = 0;

        // Initial 3x3 region: warp-uniform row-contiguous ranges.
        {
            const int x0 = max(0, cx - 1), x1 = min(G - 1, cx + 1);
            const int y0 = max(0, cy - 1), y1 = min(G - 1, cy + 1);
            for (int yy = y0; yy <= y1; yy++)
                scan_range2(s_samp, s_cs[yy * G + x0], s_cs[yy * G + x1 + 1],
                            qx0, qy0, q20, qx1, qy1, q21, b0, bi0, b1, bi1);
        }

        // Ring expansion, warp-voted (rare: P ~ e^-12.6 per query).
        int r = 1;
        while (true) {
            float db0 = 3.4e38f, db1 = 3.4e38f;
            if (cx - r > 0)     { db0 = fminf(db0, qx0 - (float)(cx - r) * h);
                                  db1 = fminf(db1, qx1 - (float)(cx - r) * h); }
            if (cx + r < G - 1) { db0 = fminf(db0, (float)(cx + r + 1) * h - qx0);
                                  db1 = fminf(db1, (float)(cx + r + 1) * h - qx1); }
            if (cy - r > 0)     { db0 = fminf(db0, qy0 - (float)(cy - r) * h);
                                  db1 = fminf(db1, qy1 - (float)(cy - r) * h); }
            if (cy + r < G - 1) { db0 = fminf(db0, (float)(cy + r + 1) * h - qy0);
                                  db1 = fminf(db1, (float)(cy + r + 1) * h - qy1); }
            const bool need = (b0 >= db0 * db0 - 1e-5f) || (b1 >= db1 * db1 - 1e-5f);
            const bool covered = (cx - r <= 0 && cx + r >= G - 1 &&
                                  cy - r <= 0 && cy + r >= G - 1);
            if (!__any_sync(0xffffffffu, need) || covered) break;
            r++;
            const int nx0 = cx - r, nx1 = cx + r, ny0 = cy - r, ny1 = cy + r;
            const int xs = max(0, nx0), xe = min(G - 1, nx1);
            if (ny0 >= 0)
                scan_range2(s_samp, s_cs[ny0 * G + xs], s_cs[ny0 * G + xe + 1],
                            qx0, qy0, q20, qx1, qy1, q21, b0, bi0, b1, bi1);
            if (ny1 <= G - 1)
                scan_range2(s_samp, s_cs[ny1 * G + xs], s_cs[ny1 * G + xe + 1],
                            qx0, qy0, q20, qx1, qy1, q21, b0, bi0, b1, bi1);
            const int ys = max(0, ny0 + 1), ye = min(G - 1, ny1 - 1);
            if (nx0 >= 0)
                for (int yy = ys; yy <= ye; yy++)
                    scan_range2(s_samp, s_cs[yy * G + nx0], s_cs[yy * G + nx0 + 1],
                                qx0, qy0, q20, qx1, qy1, q21, b0, bi0, b1, bi1);
            if (nx1 <= G - 1)
                for (int yy = ys; yy <= ye; yy++)
                    scan_range2(s_samp, s_cs[yy * G + nx1], s_cs[yy * G + nx1 + 1],
                                qx0, qy0, q20, qx1, qy1, q21, b0, bi0, b1, bi1);
        }

        if (a0) { s_bi[w][i0] = bi0; s_orig[w][i0] = __float_as_int(qs0.w); }
        if (a1) { s_bi[w][i1] = bi1; s_orig[w][i1] = __float_as_int(qs1.w); }
    }
    __syncwarp();

    // Epilogue: per-warp gather/scatter, 2 queries per iter (16 lanes, 256B each).
    const float4* __restrict__ sv4  = reinterpret_cast<const float4*>(sample_vals);
    float4* __restrict__       out4 = reinterpret_cast<float4*>(out);
    const int V4 = NDV / 4;  // 16

    for (int t = 0; t < n; t += 2) {
        const int idx = t + (lane >> 4);
        if (idx < n) {
            const int s  = s_bi[w][idx];
            const int oq = s_orig[w][idx];
            const int v  = lane & 15;
            out4[(oq * NB + b) * V4 + v] = sv4[(s * NB + b) * V4 + v];
        }
    }
}

extern "C" void kernel_launch(void* const* d_in, const int* in_sizes, int n_in,
                              void* d_out, int out_size)
{
    const float* sample_vals  = (const float*)d_in[0];  // [1024, 16, 64]
    const float* sample_posns = (const float*)d_in[1];  // [1024, 16, 2]
    const float* query_posns  = (const float*)d_in[2];  // [8192, 16, 2]
    float* out = (float*)d_out;                          // [8192, 16, 64]

    k1_bucket<<<NQ * NB / 256, 256>>>(query_posns);              // 512 blocks, ~2 us
    nn_search<<<NB * 32, 256>>>(sample_vals, sample_posns, out); // 512 blocks
}

// round 15
// speedup vs baseline: 1.8690x; 1.8690x over previous
#include <cuda_runtime.h>

#define NS   1024
#define NB   16
#define NQ   8192
#define NDV  64
#define G    16
#define NC   (G * G)
#define QCAP 96
#define NBLK 528            // 16 bin blocks + 512 bucket/search blocks

// Scratch (allocation-free rule: __device__ globals).
__device__ float4 g_sorted[NB][NS];            // (-2sx,-2sy,s2,idx-bits), cell-sorted
__device__ int    g_cellStart[NB][NC + 1];
__device__ float4 g_qbuck[NB][NC * QCAP];      // bucketed queries (qx,qy,q2,orig-bits)
__device__ int    g_qcnt[NB][NC];              // zero at load; consumed->zeroed each run
__device__ int    g_arrive, g_done;            // barrier state; self-resetting

union SmemU {
    struct { int cnt[NC]; int wsum[8]; int cur[NC]; } p1;      // binning blocks
    struct {
        float4 samp[NS];                                        // 16 KB
        int    cs[NC + 1];
        int    bi[8][QCAP];
        int    orig[8][QCAP];
    } p2;                                                       // ~23.5 KB
};

__device__ __forceinline__ void scan_range2(const float4* __restrict__ samp,
                                            int s0, int s1,
                                            float qx0, float qy0, float q20,
                                            float qx1, float qy1, float q21,
                                            float& b0, int& i0r,
                                            float& b1, int& i1r)
{
    for (int k = s0; k < s1; k++) {
        const float4 v = samp[k];             // warp-uniform address -> LDS broadcast
        const int idx = __float_as_int(v.w);
        // EXACT reference rounding: t = fma(qy,-2sy, qx*(-2sx)); d = (q2 + t) + s2
        const float t0 = __fmaf_rn(qy0, v.y, __fmul_rn(qx0, v.x));
        const float d0 = __fadd_rn(__fadd_rn(q20, t0), v.z);
        if (d0 < b0 || (d0 == b0 && idx < i0r)) { b0 = d0; i0r = idx; }
        const float t1 = __fmaf_rn(qy1, v.y, __fmul_rn(qx1, v.x));
        const float d1 = __fadd_rn(__fadd_rn(q21, t1), v.z);
        if (d1 < b1 || (d1 == b1 && idx < i1r)) { b1 = d1; i1r = idx; }
    }
}

__global__ __launch_bounds__(256)
void nn_fused(const float* __restrict__ sample_vals,    // [NS, NB, NDV]
              const float* __restrict__ sample_posns,   // [NS, NB, 2]
              const float* __restrict__ query_posns,    // [NQ, NB, 2]
              float* __restrict__ out)                  // [NQ, NB, NDV]
{
    __shared__ SmemU sm;

    const int tid  = threadIdx.x;
    const int lane = tid & 31;
    const int w    = tid >> 5;

    // ============== PHASE 1 (disjoint block roles -> short critical path) =======
    if (blockIdx.x < NB) {
        // ---- sample binning only (blocks 0..15, one per batch) ----
        const int b = blockIdx.x;
        sm.p1.cnt[tid] = 0;
        __syncthreads();

        float2 p[4];
        int    cell[4];
#pragma unroll
        for (int k = 0; k < 4; k++) {
            const int s = tid + k * 256;
            p[k] = *reinterpret_cast<const float2*>(sample_posns + (s * NB + b) * 2);
            int cx = (int)(p[k].x * G); cx = cx < 0 ? 0 : (cx > G - 1 ? G - 1 : cx);
            int cy = (int)(p[k].y * G); cy = cy < 0 ? 0 : (cy > G - 1 ? G - 1 : cy);
            cell[k] = cy * G + cx;
            atomicAdd(&sm.p1.cnt[cell[k]], 1);
        }
        __syncthreads();

        const int cnt = sm.p1.cnt[tid];
        int incl = cnt;
#pragma unroll
        for (int ofs = 1; ofs < 32; ofs <<= 1) {
            const int t = __shfl_up_sync(0xffffffffu, incl, ofs);
            if (lane >= ofs) incl += t;
        }
        if (lane == 31) sm.p1.wsum[w] = incl;
        __syncthreads();
        if (w == 0 && lane < 8) {
            int x = sm.p1.wsum[lane];
#pragma unroll
            for (int ofs = 1; ofs < 8; ofs <<= 1) {
                const int t = __shfl_up_sync(0xffu, x, ofs);
                if (lane >= ofs) x += t;
            }
            sm.p1.wsum[lane] = x;
        }
        __syncthreads();
        const int excl = incl - cnt + (w > 0 ? sm.p1.wsum[w - 1] : 0);
        sm.p1.cur[tid] = excl;
        g_cellStart[b][tid] = excl;
        if (tid == 0) g_cellStart[b][NC] = NS;
        __syncthreads();

#pragma unroll
        for (int k = 0; k < 4; k++) {
            const int s   = tid + k * 256;
            const int pos = atomicAdd(&sm.p1.cur[cell[k]], 1);
            // s2 with reference rounding: mul, mul, add. -2 fold bit-exact (pow2).
            const float s2 = __fadd_rn(__fmul_rn(p[k].x, p[k].x), __fmul_rn(p[k].y, p[k].y));
            g_sorted[b][pos] = make_float4(-2.0f * p[k].x, -2.0f * p[k].y, s2, __int_as_float(s));
        }
    } else {
        // ---- query bucketing only (blocks 16..527, exactly NQ*NB queries) ----
        const int j = (blockIdx.x - NB) * 256 + tid;    // linear -> coalesced
        const float2 p = *reinterpret_cast<const float2*>(query_posns + 2 * j);
        const int b = j & (NB - 1);
        const int q = j >> 4;
        int cx = (int)(p.x * G); cx = cx < 0 ? 0 : (cx > G - 1 ? G - 1 : cx);
        int cy = (int)(p.y * G); cy = cy < 0 ? 0 : (cy > G - 1 ? G - 1 : cy);
        const int c = cy * G + cx;
        const int slot = atomicAdd(&g_qcnt[b][c], 1);
        if (slot < QCAP) {
            const float q2 = __fadd_rn(__fmul_rn(p.x, p.x), __fmul_rn(p.y, p.y));
            g_qbuck[b][c * QCAP + slot] = make_float4(p.x, p.y, q2, __int_as_float(q));
        }
    }

    // ============== GLOBAL BARRIER (replay-safe; 528 blocks all resident) ========
    __syncthreads();
    if (tid == 0) {
        __threadfence();
        atomicAdd(&g_arrive, 1);
    }

    if (blockIdx.x >= 512) {
        // surplus bucket blocks: arrive, mark done, exit (no phase-2 role)
        if (tid == 0) {
            const int d = atomicAdd(&g_done, 1);
            if (d == NBLK - 1) { g_arrive = 0; g_done = 0; __threadfence(); }
        }
        return;
    }

    if (tid == 0) {
        while (*(volatile int*)&g_arrive < NBLK) __nanosleep(64);
        __threadfence();
    }
    __syncthreads();

    // ============== PHASE 2: warp-per-cell exact 1-NN (QPT=2) ===================
    const int b    = blockIdx.x >> 5;
    const int grp  = blockIdx.x & 31;
    const int cell = grp * 8 + w;
    const int cx   = cell & (G - 1);
    const int cy   = cell >> 4;

    int n = 0;
    if (lane == 0) n = atomicExch(&g_qcnt[b][cell], 0);   // consume + reset invariant
    n = __shfl_sync(0xffffffffu, n, 0);
    if (n > QCAP) n = QCAP;

#pragma unroll
    for (int i = tid; i < NS; i += 256) sm.p2.samp[i] = g_sorted[b][i];
    if (tid < NC) sm.p2.cs[tid] = g_cellStart[b][tid];
    if (tid == 0) sm.p2.cs[NC] = NS;
    __syncthreads();

    const float h = 1.0f / G;
    const float4* __restrict__ qb = &g_qbuck[b][cell * QCAP];

    for (int base = 0; base < n; base += 64) {           // one pass: P(n>64) ~ 6e-9
        const int  i0 = base + lane;
        const int  i1 = base + 32 + lane;
        const bool a0 = (i0 < n);
        const bool a1 = (i1 < n);
        const float4 qs0 = qb[a0 ? i0 : 0];
        const float4 qs1 = qb[a1 ? i1 : 0];
        const float qx0 = qs0.x, qy0 = qs0.y, q20 = qs0.z;
        const float qx1 = qs1.x, qy1 = qs1.y, q21 = qs1.z;

        float b0 = a0 ? __int_as_float(0x7f800000) : __int_as_float(0xff800000);
        float b1 = a1 ? __int_as_float(0x7f800000) : __int_as_float(0xff800000);
        int  bi0 = 0, bi1 = 0;

        {   // initial 3x3 region: warp-uniform row-contiguous ranges
            const int x0 = max(0, cx - 1), x1 = min(G - 1, cx + 1);
            const int y0 = max(0, cy - 1), y1 = min(G - 1, cy + 1);
            for (int yy = y0; yy <= y1; yy++)
                scan_range2(sm.p2.samp, sm.p2.cs[yy * G + x0], sm.p2.cs[yy * G + x1 + 1],
                            qx0, qy0, q20, qx1, qy1, q21, b0, bi0, b1, bi1);
        }

        // Ring expansion, warp-voted (rare: P ~ e^-12.6 per query).
        int r = 1;
        while (true) {
            float db0 = 3.4e38f, db1 = 3.4e38f;
            if (cx - r > 0)     { db0 = fminf(db0, qx0 - (float)(cx - r) * h);
                                  db1 = fminf(db1, qx1 - (float)(cx - r) * h); }
            if (cx + r < G - 1) { db0 = fminf(db0, (float)(cx + r + 1) * h - qx0);
                                  db1 = fminf(db1, (float)(cx + r + 1) * h - qx1); }
            if (cy - r > 0)     { db0 = fminf(db0, qy0 - (float)(cy - r) * h);
                                  db1 = fminf(db1, qy1 - (float)(cy - r) * h); }
            if (cy + r < G - 1) { db0 = fminf(db0, (float)(cy + r + 1) * h - qy0);
                                  db1 = fminf(db1, (float)(cy + r + 1) * h - qy1); }
            const bool need = (b0 >= db0 * db0 - 1e-5f) || (b1 >= db1 * db1 - 1e-5f);
            const bool covered = (cx - r <= 0 && cx + r >= G - 1 &&
                                  cy - r <= 0 && cy + r >= G - 1);
            if (!__any_sync(0xffffffffu, need) || covered) break;
            r++;
            const int nx0 = cx - r, nx1 = cx + r, ny0 = cy - r, ny1 = cy + r;
            const int xs = max(0, nx0), xe = min(G - 1, nx1);
            if (ny0 >= 0)
                scan_range2(sm.p2.samp, sm.p2.cs[ny0 * G + xs], sm.p2.cs[ny0 * G + xe + 1],
                            qx0, qy0, q20, qx1, qy1, q21, b0, bi0, b1, bi1);
            if (ny1 <= G - 1)
                scan_range2(sm.p2.samp, sm.p2.cs[ny1 * G + xs], sm.p2.cs[ny1 * G + xe + 1],
                            qx0, qy0, q20, qx1, qy1, q21, b0, bi0, b1, bi1);
            const int ys = max(0, ny0 + 1), ye = min(G - 1, ny1 - 1);
            if (nx0 >= 0)
                for (int yy = ys; yy <= ye; yy++)
                    scan_range2(sm.p2.samp, sm.p2.cs[yy * G + nx0], sm.p2.cs[yy * G + nx0 + 1],
                                qx0, qy0, q20, qx1, qy1, q21, b0, bi0, b1, bi1);
            if (nx1 <= G - 1)
                for (int yy = ys; yy <= ye; yy++)
                    scan_range2(sm.p2.samp, sm.p2.cs[yy * G + nx1], sm.p2.cs[yy * G + nx1 + 1],
                                qx0, qy0, q20, qx1, qy1, q21, b0, bi0, b1, bi1);
        }

        if (a0) { sm.p2.bi[w][i0] = bi0; sm.p2.orig[w][i0] = __float_as_int(qs0.w); }
        if (a1) { sm.p2.bi[w][i1] = bi1; sm.p2.orig[w][i1] = __float_as_int(qs1.w); }
    }
    __syncwarp();

    // ---- epilogue: gather/scatter with MLP=4 (4 independent LDG.128 in flight) ----
    const float4* __restrict__ sv4  = reinterpret_cast<const float4*>(sample_vals);
    float4* __restrict__       out4 = reinterpret_cast<float4*>(out);
    const int V4 = NDV / 4;  // 16
    const int vl = lane & 15;

    for (int t = 0; t < n; t += 8) {
        float4 v[4];
        int    oq[4];
        bool   act[4];
#pragma unroll
        for (int u = 0; u < 4; u++) {
            const int idx = t + 2 * u + (lane >> 4);
            act[u] = (idx < n);
            if (act[u]) {
                const int s = sm.p2.bi[w][idx];
                oq[u] = sm.p2.orig[w][idx];
                v[u]  = sv4[(s * NB + b) * V4 + vl];
            }
        }
#pragma unroll
        for (int u = 0; u < 4; u++)
            if (act[u]) out4[(oq[u] * NB + b) * V4 + vl] = v[u];
    }

    // ============== barrier state reset for next graph replay ====================
    __syncthreads();
    if (tid == 0) {
        const int d = atomicAdd(&g_done, 1);
        if (d == NBLK - 1) { g_arrive = 0; g_done = 0; __threadfence(); }
    }
}

extern "C" void kernel_launch(void* const* d_in, const int* in_sizes, int n_in,
                              void* d_out, int out_size)
{
    const float* sample_vals  = (const float*)d_in[0];  // [1024, 16, 64]
    const float* sample_posns = (const float*)d_in[1];  // [1024, 16, 2]
    const float* query_posns  = (const float*)d_in[2];  // [8192, 16, 2]
    float* out = (float*)d_out;                          // [8192, 16, 64]

    nn_fused<<<NBLK, 256>>>(sample_vals, sample_posns, query_posns, out);
}

// round 17
// speedup vs baseline: 1.8889x; 1.0107x over previous
#include <cuda_runtime.h>
#include <cstdint>

#define NS   1024
#define NB   16
#define NQ   8192
#define NDV  64
#define G    16
#define NC   (G * G)
#define QCAP 96
#define THREADS 512
#define NBLK 272            // 16 bin blocks + 256 bucket/search blocks

// Scratch (allocation-free rule: __device__ globals).
__device__ float4 g_sorted[NB][NS];                 // (-2sx,-2sy,s2,idx-bits), cell-sorted
__device__ __align__(16) int g_cellStart[NB][272];  // [0..256] used; padded to 16B multiple
__device__ float4 g_qbuck[NB][NC * QCAP];           // bucketed queries (qx,qy,q2,orig-bits)
__device__ int    g_qcnt[NB][NC];                   // zero at load; consumed->zeroed each run
__device__ int    g_arrive, g_done;                 // barrier state; self-resetting

struct P1 { int cnt[NC]; int wsum[8]; int cur[NC]; };
struct P2 {
    float4 samp[NS];        // 16384 B (bulk-copy dst, 16B aligned)
    int    cs[272];         // 1088 B (bulk-copy dst)
    int    bi[16][QCAP];
    int    orig[16][QCAP];
};
union SmemU { P1 p1; P2 p2; };

__device__ __forceinline__ uint32_t sa(const void* p) {
    return (uint32_t)__cvta_generic_to_shared(p);
}

__device__ __forceinline__ void scan_range2(const float4* __restrict__ samp,
                                            int s0, int s1,
                                            float qx0, float qy0, float q20,
                                            float qx1, float qy1, float q21,
                                            float& b0, int& i0r,
                                            float& b1, int& i1r)
{
    for (int k = s0; k < s1; k++) {
        const float4 v = samp[k];             // warp-uniform address -> LDS broadcast
        const int idx = __float_as_int(v.w);
        // EXACT reference rounding: t = fma(qy,-2sy, qx*(-2sx)); d = (q2 + t) + s2
        const float t0 = __fmaf_rn(qy0, v.y, __fmul_rn(qx0, v.x));
        const float d0 = __fadd_rn(__fadd_rn(q20, t0), v.z);
        if (d0 < b0 || (d0 == b0 && idx < i0r)) { b0 = d0; i0r = idx; }
        const float t1 = __fmaf_rn(qy1, v.y, __fmul_rn(qx1, v.x));
        const float d1 = __fadd_rn(__fadd_rn(q21, t1), v.z);
        if (d1 < b1 || (d1 == b1 && idx < i1r)) { b1 = d1; i1r = idx; }
    }
}

__global__ __launch_bounds__(THREADS)
void nn_fused(const float* __restrict__ sample_vals,    // [NS, NB, NDV]
              const float* __restrict__ sample_posns,   // [NS, NB, 2]
              const float* __restrict__ query_posns,    // [NQ, NB, 2]
              float* __restrict__ out)                  // [NQ, NB, NDV]
{
    __shared__ SmemU sm;
    __shared__ uint64_t s_mbar;

    const int tid  = threadIdx.x;
    const int lane = tid & 31;
    const int w    = tid >> 5;              // warp 0..15

    // ===================== PHASE 1 (disjoint roles) =============================
    if (blockIdx.x < NB) {
        // ---- sample binning only (blocks 0..15, one per batch; 2 samples/thread) ----
        const int b = blockIdx.x;
        if (tid < NC) sm.p1.cnt[tid] = 0;
        __syncthreads();

        float2 p[2];
        int    cell[2];
#pragma unroll
        for (int k = 0; k < 2; k++) {
            const int s = tid + k * THREADS;
            p[k] = *reinterpret_cast<const float2*>(sample_posns + (s * NB + b) * 2);
            int cx = (int)(p[k].x * G); cx = cx < 0 ? 0 : (cx > G - 1 ? G - 1 : cx);
            int cy = (int)(p[k].y * G); cy = cy < 0 ? 0 : (cy > G - 1 ? G - 1 : cy);
            cell[k] = cy * G + cx;
            atomicAdd(&sm.p1.cnt[cell[k]], 1);
        }
        __syncthreads();

        int cnt = 0, incl = 0;
        if (tid < NC) {                      // warps 0..7 fully active
            cnt = sm.p1.cnt[tid];
            incl = cnt;
#pragma unroll
            for (int ofs = 1; ofs < 32; ofs <<= 1) {
                const int t = __shfl_up_sync(0xffffffffu, incl, ofs);
                if (lane >= ofs) incl += t;
            }
            if (lane == 31) sm.p1.wsum[w] = incl;
        }
        __syncthreads();
        if (w == 0 && lane < 8) {
            int x = sm.p1.wsum[lane];
#pragma unroll
            for (int ofs = 1; ofs < 8; ofs <<= 1) {
                const int t = __shfl_up_sync(0xffu, x, ofs);
                if (lane >= ofs) x += t;
            }
            sm.p1.wsum[lane] = x;
        }
        __syncthreads();
        if (tid < NC) {
            const int excl = incl - cnt + (w > 0 ? sm.p1.wsum[w - 1] : 0);
            sm.p1.cur[tid] = excl;
            g_cellStart[b][tid] = excl;
        }
        if (tid == 0) g_cellStart[b][NC] = NS;
        __syncthreads();

#pragma unroll
        for (int k = 0; k < 2; k++) {
            const int s   = tid + k * THREADS;
            const int pos = atomicAdd(&sm.p1.cur[cell[k]], 1);
            // s2 with reference rounding: mul, mul, add. -2 fold bit-exact (pow2).
            const float s2 = __fadd_rn(__fmul_rn(p[k].x, p[k].x), __fmul_rn(p[k].y, p[k].y));
            g_sorted[b][pos] = make_float4(-2.0f * p[k].x, -2.0f * p[k].y, s2, __int_as_float(s));
        }

        // arrive + done, then exit (bin blocks have no phase-2 role)
        __syncthreads();
        if (tid == 0) {
            __threadfence();
            atomicAdd(&g_arrive, 1);
            const int d = atomicAdd(&g_done, 1);
            if (d == NBLK - 1) { g_arrive = 0; g_done = 0; __threadfence(); }
        }
        return;
    }

    // ---- query bucketing (blocks 16..271; 512 queries each = exactly NQ*NB) ----
    if (tid == 0) {
        asm volatile("mbarrier.init.shared.b64 [%0], 1;" :: "r"(sa(&s_mbar)) : "memory");
    }
    {
        const int j = (blockIdx.x - NB) * THREADS + tid;    // linear -> coalesced
        const float2 p = *reinterpret_cast<const float2*>(query_posns + 2 * j);
        const int b = j & (NB - 1);
        const int q = j >> 4;
        int cx = (int)(p.x * G); cx = cx < 0 ? 0 : (cx > G - 1 ? G - 1 : cx);
        int cy = (int)(p.y * G); cy = cy < 0 ? 0 : (cy > G - 1 ? G - 1 : cy);
        const int c = cy * G + cx;
        const int slot = atomicAdd(&g_qcnt[b][c], 1);
        if (slot < QCAP) {
            const float q2 = __fadd_rn(__fmul_rn(p.x, p.x), __fmul_rn(p.y, p.y));
            g_qbuck[b][c * QCAP + slot] = make_float4(p.x, p.y, q2, __int_as_float(q));
        }
    }

    // ===================== GLOBAL BARRIER (all 272 blocks resident) ==============
    __syncthreads();
    if (tid == 0) {
        __threadfence();
        atomicAdd(&g_arrive, 1);
        while (*(volatile int*)&g_arrive < NBLK) __nanosleep(64);
        __threadfence();
        // order prior generic-proxy global writes before async-proxy bulk reads
        asm volatile("fence.proxy.async;" ::: "memory");
    }
    __syncthreads();

    // ===================== PHASE 2: warp-per-cell exact 1-NN =====================
    const int sblk = blockIdx.x - NB;       // 0..255
    const int b    = sblk >> 4;             // batch
    const int grp  = sblk & 15;             // grid row
    const int cell = grp * G + w;           // this warp's cell (cy=grp, cx=w)
    const int cx   = w;
    const int cy   = grp;

    // One bulk DMA stages samples + cellStart into SMEM (replaces ~256-instr loop).
    if (tid == 0) {
        const uint32_t mb = sa(&s_mbar);
        asm volatile("mbarrier.arrive.expect_tx.shared.b64 _, [%0], %1;"
                     :: "r"(mb), "r"(16384u + 1088u) : "memory");
        asm volatile("cp.async.bulk.shared::cta.global.mbarrier::complete_tx::bytes "
                     "[%0], [%1], %2, [%3];"
                     :: "r"(sa(sm.p2.samp)), "l"((const void*)g_sorted[b]),
                        "r"(16384u), "r"(mb) : "memory");
        asm volatile("cp.async.bulk.shared::cta.global.mbarrier::complete_tx::bytes "
                     "[%0], [%1], %2, [%3];"
                     :: "r"(sa(sm.p2.cs)), "l"((const void*)g_cellStart[b]),
                        "r"(1088u), "r"(mb) : "memory");
    }

    // Overlap: consume this cell's query count while DMA flies.
    int n = 0;
    if (lane == 0) n = atomicExch(&g_qcnt[b][cell], 0);   // consume + reset invariant
    n = __shfl_sync(0xffffffffu, n, 0);
    if (n > QCAP) n = QCAP;

    // Wait for DMA completion (parity 0; smem barrier is fresh every launch).
    {
        const uint32_t mb = sa(&s_mbar);
        unsigned ok = 0;
        while (!ok) {
            asm volatile(
                "{\n\t.reg .pred p;\n\t"
                "mbarrier.try_wait.parity.acquire.cta.shared::cta.b64 p, [%1], %2, 0x989680;\n\t"
                "selp.b32 %0, 1, 0, p;\n\t}"
                : "=r"(ok) : "r"(mb), "r"(0u) : "memory");
        }
    }

    const float h = 1.0f / G;
    const float4* __restrict__ qb = &g_qbuck[b][cell * QCAP];

    for (int base = 0; base < n; base += 64) {           // one pass: P(n>64) ~ 6e-9
        const int  i0 = base + lane;
        const int  i1 = base + 32 + lane;
        const bool a0 = (i0 < n);
        const bool a1 = (i1 < n);
        const float4 qs0 = qb[a0 ? i0 : 0];
        const float4 qs1 = qb[a1 ? i1 : 0];
        const float qx0 = qs0.x, qy0 = qs0.y, q20 = qs0.z;
        const float qx1 = qs1.x, qy1 = qs1.y, q21 = qs1.z;

        float b0 = a0 ? __int_as_float(0x7f800000) : __int_as_float(0xff800000);
        float b1 = a1 ? __int_as_float(0x7f800000) : __int_as_float(0xff800000);
        int  bi0 = 0, bi1 = 0;

        {   // initial 3x3 region: warp-uniform row-contiguous ranges
            const int x0 = max(0, cx - 1), x1 = min(G - 1, cx + 1);
            const int y0 = max(0, cy - 1), y1 = min(G - 1, cy + 1);
            for (int yy = y0; yy <= y1; yy++)
                scan_range2(sm.p2.samp, sm.p2.cs[yy * G + x0], sm.p2.cs[yy * G + x1 + 1],
                            qx0, qy0, q20, qx1, qy1, q21, b0, bi0, b1, bi1);
        }

        // Ring expansion, warp-voted (rare: P ~ e^-12.6 per query).
        int r = 1;
        while (true) {
            float db0 = 3.4e38f, db1 = 3.4e38f;
            if (cx - r > 0)     { db0 = fminf(db0, qx0 - (float)(cx - r) * h);
                                  db1 = fminf(db1, qx1 - (float)(cx - r) * h); }
            if (cx + r < G - 1) { db0 = fminf(db0, (float)(cx + r + 1) * h - qx0);
                                  db1 = fminf(db1, (float)(cx + r + 1) * h - qx1); }
            if (cy - r > 0)     { db0 = fminf(db0, qy0 - (float)(cy - r) * h);
                                  db1 = fminf(db1, qy1 - (float)(cy - r) * h); }
            if (cy + r < G - 1) { db0 = fminf(db0, (float)(cy + r + 1) * h - qy0);
                                  db1 = fminf(db1, (float)(cy + r + 1) * h - qy1); }
            const bool need = (b0 >= db0 * db0 - 1e-5f) || (b1 >= db1 * db1 - 1e-5f);
            const bool covered = (cx - r <= 0 && cx + r >= G - 1 &&
                                  cy - r <= 0 && cy + r >= G - 1);
            if (!__any_sync(0xffffffffu, need) || covered) break;
            r++;
            const int nx0 = cx - r, nx1 = cx + r, ny0 = cy - r, ny1 = cy + r;
            const int xs = max(0, nx0), xe = min(G - 1, nx1);
            if (ny0 >= 0)
                scan_range2(sm.p2.samp, sm.p2.cs[ny0 * G + xs], sm.p2.cs[ny0 * G + xe + 1],
                            qx0, qy0, q20, qx1, qy1, q21, b0, bi0, b1, bi1);
            if (ny1 <= G - 1)
                scan_range2(sm.p2.samp, sm.p2.cs[ny1 * G + xs], sm.p2.cs[ny1 * G + xe + 1],
                            qx0, qy0, q20, qx1, qy1, q21, b0, bi0, b1, bi1);
            const int ys = max(0, ny0 + 1), ye = min(G - 1, ny1 - 1);
            if (nx0 >= 0)
                for (int yy = ys; yy <= ye; yy++)
                    scan_range2(sm.p2.samp, sm.p2.cs[yy * G + nx0], sm.p2.cs[yy * G + nx0 + 1],
                                qx0, qy0, q20, qx1, qy1, q21, b0, bi0, b1, bi1);
            if (nx1 <= G - 1)
                for (int yy = ys; yy <= ye; yy++)
                    scan_range2(sm.p2.samp, sm.p2.cs[yy * G + nx1], sm.p2.cs[yy * G + nx1 + 1],
                                qx0, qy0, q20, qx1, qy1, q21, b0, bi0, b1, bi1);
        }

        if (a0) { sm.p2.bi[w][i0] = bi0; sm.p2.orig[w][i0] = __float_as_int(qs0.w); }
        if (a1) { sm.p2.bi[w][i1] = bi1; sm.p2.orig[w][i1] = __float_as_int(qs1.w); }
    }
    __syncwarp();

    // ---- epilogue: gather/scatter with MLP=4 (4 independent LDG.128 in flight) ----
    const float4* __restrict__ sv4  = reinterpret_cast<const float4*>(sample_vals);
    float4* __restrict__       out4 = reinterpret_cast<float4*>(out);
    const int V4 = NDV / 4;  // 16
    const int vl = lane & 15;

    for (int t = 0; t < n; t += 8) {
        float4 v[4];
        int    oq[4];
        bool   act[4];
#pragma unroll
        for (int u = 0; u < 4; u++) {
            const int idx = t + 2 * u + (lane >> 4);
            act[u] = (idx < n);
            if (act[u]) {
                const int s = sm.p2.bi[w][idx];
                oq[u] = sm.p2.orig[w][idx];
                v[u]  = sv4[(s * NB + b) * V4 + vl];
            }
        }
#pragma unroll
        for (int u = 0; u < 4; u++)
            if (act[u]) out4[(oq[u] * NB + b) * V4 + vl] = v[u];
    }

    // ===================== barrier state reset for next graph replay =============
    __syncthreads();
    if (tid == 0) {
        const int d = atomicAdd(&g_done, 1);
        if (d == NBLK - 1) { g_arrive = 0; g_done = 0; __threadfence(); }
    }
}

extern "C" void kernel_launch(void* const* d_in, const int* in_sizes, int n_in,
                              void* d_out, int out_size)
{
    const float* sample_vals  = (const float*)d_in[0];  // [1024, 16, 64]
    const float* sample_posns = (const float*)d_in[1];  // [1024, 16, 2]
    const float* query_posns  = (const float*)d_in[2];  // [8192, 16, 2]
    float* out = (float*)d_out;                          // [8192, 16, 64]

    nn_fused<<<NBLK, THREADS>>>(sample_vals, sample_posns, query_posns, out);
}